// round 6
// baseline (speedup 1.0000x reference)
#include <cuda_runtime.h>
#include <cstdint>

// GeometricLoss: N=8192 2D points, k=5 NN (excl. self), mean of 16-ch L2 norms
// of output differences.
// R6: one query per warp (QPW=1), TPB=1024, 256 CTAs = perfect single wave at
// 2 CTAs/SM (regs capped to 32, smem split xy[64KB]+h[32KB]=96KB).
// Rank by f(p)=0.5|p|^2 - q.p; two-tile min-gated ballot; distributed warp
// top-6; seeded tile 0; fused last-block reduction.

#define NPTS 8192
#define NCH 16
#define KNN 5
#define TPB 1024
#define WPB (TPB / 32)              // 32 warps per block = 32 queries/block
#define NBLK (NPTS / WPB)           // 256 blocks
#define FULLM 0xFFFFFFFFu
#define SENT 0xFFFFFFFFFFFFFFFFULL

__device__ float g_partial[NPTS];
__device__ unsigned g_ticket = 0;

extern __shared__ char smem_raw[];

// Monotone map: signed-float bits -> ascending u32.
__device__ __forceinline__ unsigned fmap(float f) {
    unsigned u = __float_as_uint(f);
    return (u & 0x80000000u) ? ~u : (u | 0x80000000u);
}
__device__ __forceinline__ float funmap(unsigned m) {
    unsigned u = (m & 0x80000000u) ? (m ^ 0x80000000u) : ~m;
    return __uint_as_float(u);
}

// Distributed top-6: lane r (r<6) holds rank-r key (fmap(f)<<32)|idx;
// th (replicated) is the 6th-best f. Keys unique & totally ordered ->
// exact, insertion-order-independent selection, low-index tie-break.
struct TopK {
    unsigned long long key;
    float th;
};

// Uniform insert (precondition: f < th). Sorted shift via shfl_up.
__device__ __forceinline__ void tk_insert(TopK& t, float f, int j, int lane) {
    unsigned long long nk =
        ((unsigned long long)fmap(f) << 32) | (unsigned)j;
    unsigned long long prev = __shfl_up_sync(FULLM, t.key, 1);
    bool shift = (lane > 0) && (nk < prev);
    bool take  = nk < t.key;
    t.key = shift ? prev : (take ? nk : t.key);
    t.th = funmap((unsigned)(__shfl_sync(FULLM, t.key, 5) >> 32));
}

// Slow path for a two-tile group: per ballot bit, check tile-A then tile-B
// candidate (uniform loop; th re-checked after tightening).
__device__ __forceinline__ void tk_hits2(TopK& t, unsigned msk, float fa,
                                         float fb, int jbase, int lane) {
    do {
        int src = __ffs(msk) - 1;
        msk &= msk - 1;
        float a = __shfl_sync(FULLM, fa, src);
        float b = __shfl_sync(FULLM, fb, src);
        if (a < t.th) tk_insert(t, a, jbase + src, lane);
        if (b < t.th) tk_insert(t, b, jbase + 32 + src, lane);
    } while (msk);
}

// Single-tile slow path (used for tile 1 only).
__device__ __forceinline__ void tk_hits1(TopK& t, unsigned msk, float f,
                                         int jbase, int lane) {
    do {
        int src = __ffs(msk) - 1;
        msk &= msk - 1;
        float a = __shfl_sync(FULLM, f, src);
        if (a < t.th) tk_insert(t, a, jbase + src, lane);
    } while (msk);
}

// Seed from tile 0 (candidate j = lane): 6 warp-min extraction rounds.
__device__ __forceinline__ void tk_seed(TopK& t, float f, int lane) {
    unsigned long long v =
        ((unsigned long long)fmap(f) << 32) | (unsigned)lane;
    unsigned long long mykey = SENT;
#pragma unroll
    for (int r = 0; r < 6; r++) {
        unsigned long long m = v;
#pragma unroll
        for (int off = 16; off > 0; off >>= 1) {
            unsigned long long o = __shfl_xor_sync(FULLM, m, off);
            if (o < m) m = o;
        }
        if (lane == r) mykey = m;
        if (v == m) v = SENT;  // unique keys: exactly one owner retires
    }
    t.key = mykey;
    t.th = funmap((unsigned)(__shfl_sync(FULLM, t.key, 5) >> 32));
}

__global__ __launch_bounds__(TPB, 2)
void knn_loss_kernel(const float* __restrict__ outputs,
                     const float* __restrict__ points,
                     float* __restrict__ out) {
    float2* xy_s = (float2*)smem_raw;                  // 64 KB
    float*  h_s  = (float*)(smem_raw + NPTS * 8);      // 32 KB

    const int tid = threadIdx.x;
    const int lane = tid & 31;
    const int warp = tid >> 5;

    // cooperative smem fill: xy + h = 0.5*(x^2+y^2)
    {
        const float2* src = (const float2*)points;
#pragma unroll
        for (int i = 0; i < NPTS / TPB; i++) {
            int j = tid + i * TPB;
            float2 p = src[j];
            xy_s[j] = p;
            h_s[j] = 0.5f * fmaf(p.y, p.y, p.x * p.x);
        }
    }
    __syncthreads();

    const int qi = blockIdx.x * WPB + warp;
    float2 q = ((const float2*)points)[qi];
    const float nqx = -q.x, nqy = -q.y;

    TopK t;

    // ---- seed from tile 0 ----
    {
        float2 p = xy_s[lane];
        float f = fmaf(p.x, nqx, fmaf(p.y, nqy, h_s[lane]));
        tk_seed(t, f, lane);
    }
    // ---- tile 1, single ----
    {
        int j = 32 + lane;
        float2 p = xy_s[j];
        float f = fmaf(p.x, nqx, fmaf(p.y, nqy, h_s[j]));
        unsigned m = __ballot_sync(FULLM, f < t.th);
        if (m) tk_hits1(t, m, f, 32, lane);
    }
    // ---- tiles 2..255 in pairs ----
#pragma unroll 2
    for (int tt = 2; tt < NPTS / 32; tt += 2) {
        const int jbase = tt * 32;
        int ja = jbase + lane;
        float2 pa = xy_s[ja];
        float2 pb = xy_s[ja + 32];
        float ha = h_s[ja];
        float hb = h_s[ja + 32];
        float fa = fmaf(pa.x, nqx, fmaf(pa.y, nqy, ha));
        float fb = fmaf(pb.x, nqx, fmaf(pb.y, nqy, hb));
        float fm = fminf(fa, fb);
        unsigned m = __ballot_sync(FULLM, fm < t.th);
        if (m) tk_hits2(t, m, fa, fb, jbase, lane);
    }

    // ---- epilogue: rank 0 is self; lanes 1..5 own the 5 neighbor keys ----
    {
        float s = 0.0f;
        if (lane >= 1 && lane <= KNN) {
            int nb = (int)(t.key & 0xFFFFFFFFULL);
            const float4* oq = (const float4*)(outputs + (size_t)qi * NCH);
            const float4* on = (const float4*)(outputs + (size_t)nb * NCH);
            float acc = 0.0f;
#pragma unroll
            for (int c = 0; c < NCH / 4; c++) {
                float4 a = oq[c];
                float4 bb = on[c];
                float d;
                d = a.x - bb.x; acc = fmaf(d, d, acc);
                d = a.y - bb.y; acc = fmaf(d, d, acc);
                d = a.z - bb.z; acc = fmaf(d, d, acc);
                d = a.w - bb.w; acc = fmaf(d, d, acc);
            }
            s = sqrtf(acc);
        }
#pragma unroll
        for (int off = 16; off > 0; off >>= 1)
            s += __shfl_xor_sync(FULLM, s, off);
        if (lane == 0) g_partial[qi] = s;
    }

    // ---- fused final reduction: last block to arrive does the sum ----
    __syncthreads();
    __shared__ bool is_last;
    if (tid == 0) {
        __threadfence();
        unsigned tk = atomicAdd(&g_ticket, 1);
        is_last = (tk == NBLK - 1);
    }
    __syncthreads();
    if (is_last) {
        __threadfence();
        float acc = 0.0f;
        for (int j = tid; j < NPTS; j += TPB) acc += g_partial[j];
        __shared__ float sm[TPB];
        sm[tid] = acc;
        __syncthreads();
        for (int st = TPB / 2; st > 0; st >>= 1) {
            if (tid < st) sm[tid] += sm[tid + st];
            __syncthreads();
        }
        if (tid == 0) {
            out[0] = sm[0] / (float)(NPTS * KNN);
            g_ticket = 0;  // reset for next graph replay
        }
    }
}

extern "C" void kernel_launch(void* const* d_in, const int* in_sizes, int n_in,
                              void* d_out, int out_size) {
    const float* outputs = (const float*)d_in[0];
    const float* points  = (const float*)d_in[1];
    float* out = (float*)d_out;

    const int smem_bytes = NPTS * 8 + NPTS * 4;  // 96 KB
    cudaFuncSetAttribute(knn_loss_kernel,
                         cudaFuncAttributeMaxDynamicSharedMemorySize,
                         smem_bytes);
    knn_loss_kernel<<<NBLK, TPB, smem_bytes>>>(outputs, points, out);
}